// round 4
// baseline (speedup 1.0000x reference)
#include <cuda_runtime.h>
#include <cuda_bf16.h>
#include <math.h>

// ---------------------------------------------------------------------------
// MultiHeadCrossAttention baseline (fp32, SIMT GEMMs)
//
// Shapes: B=8, N=1024, H=8, n=128 (contiguous token blocks per head),
//         SCALE=960, Cq in {64,128,256,512}.
//
// Pipeline per the reference:
//   Kt  = KVh @ Wk^T        (per b,h: 128x960x960)
//   KVt = Kt  @ Wv^T        (per b,h: 128x960x960)   (K == V)
//   per branch:
//     Qt   = Qh @ Wq^T      (per b,h: 128xCqxCq)
//     attn = Qt^T @ KVt * inv_scale   (per b,h: Cq x 960, K=128)
//     P    = softmax_s( attn * rsqrt(var_slice(attn)+eps) )   [mean cancels!]
//     out  = P @ KVt^T      (per b,h: Cq x 128, K=960), written transposed
//     y    = out @ Wo^T     (per b:   1024 x Cq, K=Cq)
// ---------------------------------------------------------------------------

#define TM 64
#define TN 64
#define TKK 16
#define PAD 4

// Scratch (static device globals: allocation-free per harness rules)
__device__ float g_Kt    [8 * 1024 * 960];      // 31.5 MB
__device__ float g_KVt   [8 * 1024 * 960];      // 31.5 MB
__device__ float g_Qt    [8 * 1024 * 512];      // 16.8 MB (max branch)
__device__ float g_attn  [64 * 512 * 960];      // 125.8 MB (max branch)
__device__ float g_outtmp[8 * 1024 * 512];      // 16.8 MB (max branch)
__device__ float g_invstd[64];

// Generic strided batched GEMM:
//   C[m*Cm + n*Cn] = alpha * sum_k A[m*Am + k*Ak] * B[n*Bn + k*Bk]
// Per batch z: A += z*sAz, B += (z % modB)*sBz, C += z*sCz.
// Requires: M % 64 == 0, N % 64 == 0, K % 16 == 0 (true for every call here).
// Either Ak==1 or Am==1 (same for B) — picks the coalesced load path.
__global__ __launch_bounds__(256) void gemm_strided(
    const float* __restrict__ A, int Am, int Ak, long sAz,
    const float* __restrict__ B, int Bn, int Bk, long sBz, int modB,
    float* __restrict__ C, int Cm, int Cn, long sCz,
    int K, float alpha)
{
    const int z = blockIdx.z;
    A += (long)z * sAz;
    B += (long)(z % modB) * sBz;
    C += (long)z * sCz;

    __shared__ float As[TKK][TM + PAD];
    __shared__ float Bs[TKK][TN + PAD];

    const int tid = threadIdx.x;         // 0..255
    const int tx  = tid & 15;            // N-direction group
    const int ty  = tid >> 4;            // M-direction group
    const int m0  = blockIdx.y * TM;
    const int n0  = blockIdx.x * TN;

    float acc[4][4] = {};

    for (int k0 = 0; k0 < K; k0 += TKK) {
        // ---- load A tile -> As[k][m] ----
        if (Ak == 1) {
            #pragma unroll
            for (int i = 0; i < 4; i++) {
                int t = tid + i * 256;
                int m = t >> 4;          // 0..63
                int k = t & 15;          // 0..15 (contiguous in gmem)
                As[k][m] = A[(long)(m0 + m) * Am + (k0 + k)];
            }
        } else { // Am == 1
            #pragma unroll
            for (int i = 0; i < 4; i++) {
                int t = tid + i * 256;
                int k = t >> 6;          // 0..15
                int m = t & 63;          // contiguous in gmem
                As[k][m] = A[(m0 + m) + (long)(k0 + k) * Ak];
            }
        }
        // ---- load B tile -> Bs[k][n] ----
        if (Bk == 1) {
            #pragma unroll
            for (int i = 0; i < 4; i++) {
                int t = tid + i * 256;
                int n = t >> 4;
                int k = t & 15;
                Bs[k][n] = B[(long)(n0 + n) * Bn + (k0 + k)];
            }
        } else { // Bn == 1
            #pragma unroll
            for (int i = 0; i < 4; i++) {
                int t = tid + i * 256;
                int k = t >> 6;
                int n = t & 63;
                Bs[k][n] = B[(n0 + n) + (long)(k0 + k) * Bk];
            }
        }
        __syncthreads();

        #pragma unroll
        for (int k = 0; k < TKK; k++) {
            float4 a4 = *reinterpret_cast<const float4*>(&As[k][ty * 4]);
            float4 b4 = *reinterpret_cast<const float4*>(&Bs[k][tx * 4]);
            float av[4] = {a4.x, a4.y, a4.z, a4.w};
            float bv[4] = {b4.x, b4.y, b4.z, b4.w};
            #pragma unroll
            for (int i = 0; i < 4; i++)
                #pragma unroll
                for (int j = 0; j < 4; j++)
                    acc[i][j] += av[i] * bv[j];
        }
        __syncthreads();
    }

    #pragma unroll
    for (int i = 0; i < 4; i++) {
        long m = m0 + ty * 4 + i;
        #pragma unroll
        for (int j = 0; j < 4; j++) {
            long n = n0 + tx * 4 + j;
            C[m * Cm + n * Cn] = alpha * acc[i][j];
        }
    }
}

// Per-(b,h) slice: inv_std = rsqrt(var + 1e-5) over Cq*960 elements (biased var).
__global__ __launch_bounds__(256) void stats_kernel(
    const float* __restrict__ attn, int elems, float* __restrict__ invstd)
{
    const int z = blockIdx.x;
    const float* p = attn + (long)z * elems;
    float s = 0.f, ss = 0.f;
    for (int i = threadIdx.x; i < elems; i += 256) {
        float v = p[i];
        s += v;
        ss += v * v;
    }
    __shared__ float shs[8], shss[8];
    #pragma unroll
    for (int o = 16; o > 0; o >>= 1) {
        s  += __shfl_xor_sync(0xffffffffu, s,  o);
        ss += __shfl_xor_sync(0xffffffffu, ss, o);
    }
    int wid = threadIdx.x >> 5, lid = threadIdx.x & 31;
    if (lid == 0) { shs[wid] = s; shss[wid] = ss; }
    __syncthreads();
    if (threadIdx.x == 0) {
        float S = 0.f, SS = 0.f;
        #pragma unroll
        for (int i = 0; i < 8; i++) { S += shs[i]; SS += shss[i]; }
        float inv_n = 1.0f / (float)elems;
        float mean = S * inv_n;
        float var  = SS * inv_n - mean * mean;
        invstd[z] = rsqrtf(var + 1e-5f);
    }
}

// Row softmax over s (length 960) of attn[c,s] * invstd[bh].
// (InstanceNorm's mean term is constant over s, so it cancels in softmax.)
__global__ __launch_bounds__(256) void softmax_kernel(
    float* __restrict__ attn, const float* __restrict__ invstd, int Cq)
{
    const int bh = blockIdx.y;
    const long row = (long)bh * Cq + blockIdx.x;
    float* p = attn + row * 960;
    const float r = invstd[bh];
    const int t = threadIdx.x;

    float v[4];
    float mx = -3.0e38f;
    #pragma unroll
    for (int i = 0; i < 4; i++) {
        int idx = t + i * 256;
        v[i] = (idx < 960) ? p[idx] * r : -3.0e38f;
        mx = fmaxf(mx, v[i]);
    }
    __shared__ float sh[8];
    #pragma unroll
    for (int o = 16; o > 0; o >>= 1) mx = fmaxf(mx, __shfl_xor_sync(0xffffffffu, mx, o));
    if ((t & 31) == 0) sh[t >> 5] = mx;
    __syncthreads();
    if (t < 32) {
        float m = (t < 8) ? sh[t] : -3.0e38f;
        #pragma unroll
        for (int o = 4; o > 0; o >>= 1) m = fmaxf(m, __shfl_xor_sync(0xffffffffu, m, o));
        if (t == 0) sh[0] = m;
    }
    __syncthreads();
    mx = sh[0];
    __syncthreads();

    float s = 0.f;
    #pragma unroll
    for (int i = 0; i < 4; i++) {
        int idx = t + i * 256;
        v[i] = (idx < 960) ? expf(v[i] - mx) : 0.f;
        s += v[i];
    }
    #pragma unroll
    for (int o = 16; o > 0; o >>= 1) s += __shfl_xor_sync(0xffffffffu, s, o);
    if ((t & 31) == 0) sh[t >> 5] = s;
    __syncthreads();
    if (t < 32) {
        float x = (t < 8) ? sh[t] : 0.f;
        #pragma unroll
        for (int o = 4; o > 0; o >>= 1) x += __shfl_xor_sync(0xffffffffu, x, o);
        if (t == 0) sh[0] = x;
    }
    __syncthreads();
    const float inv = 1.0f / sh[0];
    #pragma unroll
    for (int i = 0; i < 4; i++) {
        int idx = t + i * 256;
        if (idx < 960) p[idx] = v[i] * inv;
    }
}

static inline void launch_gemm(
    const float* A, int Am, int Ak, long sAz,
    const float* B, int Bn, int Bk, long sBz, int modB,
    float* C, int Cm, int Cn, long sCz,
    int M, int N, int K, int nbatch, float alpha)
{
    dim3 grid(N / 64, M / 64, nbatch);
    gemm_strided<<<grid, 256>>>(A, Am, Ak, sAz, B, Bn, Bk, sBz, modB,
                                C, Cm, Cn, sCz, K, alpha);
}

extern "C" void kernel_launch(void* const* d_in, const int* in_sizes, int n_in,
                              void* d_out, int out_size)
{
    (void)in_sizes; (void)n_in; (void)out_size;

    const float* Q[4]  = {(const float*)d_in[0], (const float*)d_in[1],
                          (const float*)d_in[2], (const float*)d_in[3]};
    const float* KV    = (const float*)d_in[4];
    const float* Wk    = (const float*)d_in[5];
    const float* Wv    = (const float*)d_in[6];
    const float* Wq[4] = {(const float*)d_in[7], (const float*)d_in[8],
                          (const float*)d_in[9], (const float*)d_in[10]};
    const float* Wo[4] = {(const float*)d_in[11], (const float*)d_in[12],
                          (const float*)d_in[13], (const float*)d_in[14]};
    float* out = (float*)d_out;

    float *Kt, *KVt, *Qt, *attn, *ot, *invstd;
    cudaGetSymbolAddress((void**)&Kt,     g_Kt);
    cudaGetSymbolAddress((void**)&KVt,    g_KVt);
    cudaGetSymbolAddress((void**)&Qt,     g_Qt);
    cudaGetSymbolAddress((void**)&attn,   g_attn);
    cudaGetSymbolAddress((void**)&ot,     g_outtmp);
    cudaGetSymbolAddress((void**)&invstd, g_invstd);

    const int S = 960, NSEQ = 128, BH = 64;
    const long sKV = (long)NSEQ * S;     // 122880 per (b,h)
    const float inv_scale = 1.0f / sqrtf(960.0f);

    // 1) Kt = KVh @ Wk^T   (per bh: 128x960, K=960; weight per h)
    launch_gemm(KV, S, 1, sKV,  Wk, S, 1, (long)S * S, 8,
                Kt, S, 1, sKV,  NSEQ, S, S, BH, 1.0f);
    // 2) KVt = Kt @ Wv^T
    launch_gemm(Kt, S, 1, sKV,  Wv, S, 1, (long)S * S, 8,
                KVt, S, 1, sKV, NSEQ, S, S, BH, 1.0f);

    const int  Cqs[4]    = {64, 128, 256, 512};
    const long outoff[4] = {0, 524288, 1572864, 3670016};

    for (int br = 0; br < 4; br++) {
        const int  Cq  = Cqs[br];
        const long sQ  = (long)NSEQ * Cq;    // per-(b,h) stride in Q / Qt
        const long sAt = (long)Cq * S;       // per-(b,h) stride in attn

        // 3) Qt = Qh @ Wq^T  (per bh: 128xCq, K=Cq)
        launch_gemm(Q[br], Cq, 1, sQ,  Wq[br], Cq, 1, (long)Cq * Cq, 8,
                    Qt, Cq, 1, sQ,  NSEQ, Cq, Cq, BH, 1.0f);

        // 4) attn = inv_scale * Qt^T @ KVt  (per bh: Cq x 960, K=128)
        //    A(m=c,k=n) = Qt[n*Cq + c]  -> Am=1, Ak=Cq
        //    B(n=s,k=n) = KVt[n*960 + s] -> Bn=1, Bk=960
        launch_gemm(Qt, 1, Cq, sQ,  KVt, 1, S, sKV, BH,
                    attn, S, 1, sAt,  Cq, S, NSEQ, BH, inv_scale);

        // 5) per-slice inv_std, then row softmax of attn * inv_std
        stats_kernel<<<BH, 256>>>(attn, Cq * S, invstd);
        {
            dim3 g(Cq, BH);
            softmax_kernel<<<g, 256>>>(attn, invstd, Cq);
        }

        // 6) out = P @ KVt^T  (per bh: Cq x 128, K=960), stored transposed:
        //    ot[b, h*128+n, c]  -> Cm=1, Cn=Cq, batch stride 128*Cq
        launch_gemm(attn, S, 1, sAt,  KVt, S, 1, sKV, BH,
                    ot, 1, Cq, (long)NSEQ * Cq,  Cq, NSEQ, S, BH, 1.0f);

        // 7) y = ot @ Wo^T  (per b: 1024 x Cq, K=Cq; shared weight)
        launch_gemm(ot, Cq, 1, (long)1024 * Cq,  Wo[br], Cq, 1, 0, 1,
                    out + outoff[br], Cq, 1, (long)1024 * Cq,
                    1024, Cq, Cq, 8, 1.0f);
    }
}

// round 5
// speedup vs baseline: 2.2527x; 2.2527x over previous
#include <cuda_runtime.h>
#include <cuda_bf16.h>
#include <math.h>
#include <stdint.h>

// ---------------------------------------------------------------------------
// MultiHeadCrossAttention — tf32 tensor-core GEMMs (mma.sync m16n8k8, fp32 acc)
//
// Shapes: B=8, N=1024, H=8, n=128 (contiguous token blocks per head),
//         SCALE=960, Cq in {64,128,256,512}.
//
//   Kt  = KVh @ Wk^T         (per b,h: 128x960, K=960)
//   KVt = Kt  @ Wv^T         (per b,h: 128x960, K=960)   (K == V)
//   per branch:
//     Qt   = Qh @ Wq^T       (per b,h: 128xCq,  K=Cq)
//     attn = inv_scale * Qt^T @ KVt       (per b,h: Cq x 960, K=128)
//     P    = softmax_s( attn * rsqrt(var_slice(attn)+eps) )  [mean cancels]
//     out  = P @ KVt^T       (per b,h: Cq x 128, K=960), written transposed
//     y    = out @ Wo^T      (per b:   1024 x Cq, K=Cq)
// ---------------------------------------------------------------------------

#define BM 128
#define BN 128
#define BK 16
#define SKS 20   // smem row stride in 32-bit words: 80B = 5*16B (STS.128-aligned,
                 // and r*20+c mod 32 distinct for r=0..7 -> conflict-free frags)

// Scratch (static device globals: allocation-free per harness rules)
__device__ float g_Kt    [8 * 1024 * 960];      // 31.5 MB
__device__ float g_KVt   [8 * 1024 * 960];      // 31.5 MB
__device__ float g_Qt    [8 * 1024 * 512];      // 16.8 MB
__device__ float g_attn  [64 * 512 * 960];      // 125.8 MB
__device__ float g_outtmp[8 * 1024 * 512];      // 16.8 MB
__device__ float g_part  [64 * 16 * 2];
__device__ float g_invstd[64];

__device__ __forceinline__ uint32_t f2tf(float x) {
    uint32_t r; asm("cvt.rna.tf32.f32 %0, %1;" : "=r"(r) : "f"(x)); return r;
}

__device__ __forceinline__ void mma8(float* c, const uint32_t* a, const uint32_t* b) {
    asm volatile("mma.sync.aligned.m16n8k8.row.col.f32.tf32.tf32.f32 "
        "{%0,%1,%2,%3}, {%4,%5,%6,%7}, {%8,%9}, {%0,%1,%2,%3};"
        : "+f"(c[0]), "+f"(c[1]), "+f"(c[2]), "+f"(c[3])
        : "r"(a[0]), "r"(a[1]), "r"(a[2]), "r"(a[3]), "r"(b[0]), "r"(b[1]));
}

// Load one 128x16 tile into registers. Either Xk==1 (contiguous along k:
// float4 loads) or Xm==1 (contiguous along m: 4x LDG.32, lane-coalesced).
// Rows clamped to [0, Mlim) — clamped rows feed acc rows that are never stored.
__device__ __forceinline__ void ldg_tile(
    const float* __restrict__ X, int Xm, int Xk,
    int m0, int k0, int Mlim, int tid, float* r)
{
    if (Xk == 1) {
        #pragma unroll
        for (int i = 0; i < 2; i++) {
            int q = tid + i * 256;
            int m = q >> 2, kq = q & 3;
            int mm = min(m0 + m, Mlim - 1);
            float4 v = *reinterpret_cast<const float4*>(X + (long)mm * Xm + k0 + kq * 4);
            r[i*4+0] = v.x; r[i*4+1] = v.y; r[i*4+2] = v.z; r[i*4+3] = v.w;
        }
    } else { // Xm == 1
        #pragma unroll
        for (int i = 0; i < 2; i++) {
            int q = tid + i * 256;
            int m = q & 127, kq = q >> 7;
            int mm = min(m0 + m, Mlim - 1);
            #pragma unroll
            for (int j = 0; j < 4; j++)
                r[i*4+j] = X[mm + (long)(k0 + kq * 4 + j) * Xk];
        }
    }
}

// Store staged registers to smem tile [m][k], converting fp32 -> tf32 (RNA).
__device__ __forceinline__ void sts_tile(
    uint32_t (*S)[SKS], int Xk, int tid, const float* r)
{
    #pragma unroll
    for (int i = 0; i < 2; i++) {
        int q = tid + i * 256;
        int m, kq;
        if (Xk == 1) { m = q >> 2;  kq = q & 3; }
        else         { m = q & 127; kq = q >> 7; }
        uint4 v = make_uint4(f2tf(r[i*4+0]), f2tf(r[i*4+1]),
                             f2tf(r[i*4+2]), f2tf(r[i*4+3]));
        *reinterpret_cast<uint4*>(&S[m][kq * 4]) = v;
    }
}

// Generic strided batched tf32 GEMM:
//   C[m*Cm + n*Cn] = alpha * sum_k A[m*Am + k*Ak] * B[n*Bn + k*Bk]
// Per batch z: A += z*sAz, B += (z % modB)*sBz, C += z*sCz.
// K % 16 == 0 required; M/N tails handled by clamped loads + guarded stores.
__global__ __launch_bounds__(256) void gemm_tc(
    const float* __restrict__ A, int Am, int Ak, long sAz,
    const float* __restrict__ B, int Bn, int Bk, long sBz, int modB,
    float* __restrict__ C, int Cm, int Cn, long sCz,
    int M, int N, int K, float alpha)
{
    const int z = blockIdx.z;
    A += (long)z * sAz;
    B += (long)(z % modB) * sBz;
    C += (long)z * sCz;

    __shared__ uint32_t As[2][BM][SKS];
    __shared__ uint32_t Bs[2][BN][SKS];

    const int tid  = threadIdx.x;
    const int lane = tid & 31;
    const int warp = tid >> 5;
    const int wm   = (warp & 1) * 64;   // warp M offset (2 warps in M)
    const int wn   = (warp >> 1) * 32;  // warp N offset (4 warps in N)
    const int m0   = blockIdx.y * BM;
    const int n0   = blockIdx.x * BN;

    const int gr = lane >> 2;  // groupID   (0..7)
    const int gc = lane & 3;   // tid-in-group (0..3)

    float acc[4][4][4];
    #pragma unroll
    for (int i = 0; i < 4; i++)
        #pragma unroll
        for (int j = 0; j < 4; j++)
            #pragma unroll
            for (int l = 0; l < 4; l++) acc[i][j][l] = 0.f;

    float ra[8], rb[8];

    // prologue: tile 0
    ldg_tile(A, Am, Ak, m0, 0, M, tid, ra);
    ldg_tile(B, Bn, Bk, n0, 0, N, tid, rb);
    sts_tile(As[0], Ak, tid, ra);
    sts_tile(Bs[0], Bk, tid, rb);
    __syncthreads();

    int p = 0;
    for (int k0 = BK; k0 <= K; k0 += BK) {
        const bool has_next = (k0 < K);
        if (has_next) {
            ldg_tile(A, Am, Ak, m0, k0, M, tid, ra);
            ldg_tile(B, Bn, Bk, n0, k0, N, tid, rb);
        }

        // compute on buffer p (2 k8-steps)
        #pragma unroll
        for (int ks = 0; ks < 2; ks++) {
            const int kb = ks * 8;
            uint32_t af[4][4], bf[4][2];
            #pragma unroll
            for (int mt = 0; mt < 4; mt++) {
                const int r0 = wm + mt * 16 + gr;
                af[mt][0] = As[p][r0    ][kb + gc];
                af[mt][1] = As[p][r0 + 8][kb + gc];
                af[mt][2] = As[p][r0    ][kb + gc + 4];
                af[mt][3] = As[p][r0 + 8][kb + gc + 4];
            }
            #pragma unroll
            for (int nt = 0; nt < 4; nt++) {
                const int c0 = wn + nt * 8 + gr;
                bf[nt][0] = Bs[p][c0][kb + gc];
                bf[nt][1] = Bs[p][c0][kb + gc + 4];
            }
            #pragma unroll
            for (int mt = 0; mt < 4; mt++)
                #pragma unroll
                for (int nt = 0; nt < 4; nt++)
                    mma8(acc[mt][nt], af[mt], bf[nt]);
        }

        if (has_next) {
            sts_tile(As[p ^ 1], Ak, tid, ra);
            sts_tile(Bs[p ^ 1], Bk, tid, rb);
            __syncthreads();
            p ^= 1;
        }
    }

    // epilogue (guarded)
    #pragma unroll
    for (int mt = 0; mt < 4; mt++) {
        #pragma unroll
        for (int nt = 0; nt < 4; nt++) {
            const int rr = wm + mt * 16 + gr;
            const int cc = wn + nt * 8 + gc * 2;
            #pragma unroll
            for (int h = 0; h < 2; h++) {
                const int row = m0 + rr + h * 8;
                if (row < M) {
                    const int c1 = n0 + cc, c2 = n0 + cc + 1;
                    if (c1 < N) C[(long)row * Cm + (long)c1 * Cn] = alpha * acc[mt][nt][h*2+0];
                    if (c2 < N) C[(long)row * Cm + (long)c2 * Cn] = alpha * acc[mt][nt][h*2+1];
                }
            }
        }
    }
}

// ---- InstanceNorm variance (mean cancels in softmax; only inv_std needed) ----
__global__ __launch_bounds__(256) void stats_partial(
    const float* __restrict__ attn, int elems, float* __restrict__ part)
{
    const int z = blockIdx.y, c = blockIdx.x;       // gridDim.x == 16
    const int chunk = elems / 16;
    const float* p = attn + (long)z * elems + (long)c * chunk;
    float s = 0.f, ss = 0.f;
    for (int i = threadIdx.x; i < chunk; i += 256) {
        float v = p[i];
        s += v; ss += v * v;
    }
    __shared__ float shs[8], shss[8];
    #pragma unroll
    for (int o = 16; o > 0; o >>= 1) {
        s  += __shfl_xor_sync(0xffffffffu, s,  o);
        ss += __shfl_xor_sync(0xffffffffu, ss, o);
    }
    const int wid = threadIdx.x >> 5, lid = threadIdx.x & 31;
    if (lid == 0) { shs[wid] = s; shss[wid] = ss; }
    __syncthreads();
    if (threadIdx.x == 0) {
        float S = 0.f, SS = 0.f;
        #pragma unroll
        for (int i = 0; i < 8; i++) { S += shs[i]; SS += shss[i]; }
        part[(z * 16 + c) * 2 + 0] = S;
        part[(z * 16 + c) * 2 + 1] = SS;
    }
}

__global__ void stats_final(const float* __restrict__ part,
                            float* __restrict__ invstd, float inv_n)
{
    const int z = threadIdx.x;
    if (z < 64) {
        float s = 0.f, ss = 0.f;
        #pragma unroll
        for (int i = 0; i < 16; i++) {
            s  += part[(z * 16 + i) * 2 + 0];
            ss += part[(z * 16 + i) * 2 + 1];
        }
        const float m = s * inv_n;
        const float var = ss * inv_n - m * m;
        invstd[z] = rsqrtf(var + 1e-5f);
    }
}

// Row softmax over s (length 960) of attn[c,s] * invstd[bh].
__global__ __launch_bounds__(256) void softmax_kernel(
    float* __restrict__ attn, const float* __restrict__ invstd, int Cq)
{
    const int bh = blockIdx.y;
    const long row = (long)bh * Cq + blockIdx.x;
    float* p = attn + row * 960;
    const float r = invstd[bh];
    const int t = threadIdx.x;

    float v[4];
    float mx = -3.0e38f;
    #pragma unroll
    for (int i = 0; i < 4; i++) {
        int idx = t + i * 256;
        v[i] = (idx < 960) ? p[idx] * r : -3.0e38f;
        mx = fmaxf(mx, v[i]);
    }
    __shared__ float sh[8];
    #pragma unroll
    for (int o = 16; o > 0; o >>= 1) mx = fmaxf(mx, __shfl_xor_sync(0xffffffffu, mx, o));
    if ((t & 31) == 0) sh[t >> 5] = mx;
    __syncthreads();
    if (t < 32) {
        float m = (t < 8) ? sh[t] : -3.0e38f;
        #pragma unroll
        for (int o = 4; o > 0; o >>= 1) m = fmaxf(m, __shfl_xor_sync(0xffffffffu, m, o));
        if (t == 0) sh[0] = m;
    }
    __syncthreads();
    mx = sh[0];
    __syncthreads();

    float s = 0.f;
    #pragma unroll
    for (int i = 0; i < 4; i++) {
        int idx = t + i * 256;
        v[i] = (idx < 960) ? expf(v[i] - mx) : 0.f;
        s += v[i];
    }
    #pragma unroll
    for (int o = 16; o > 0; o >>= 1) s += __shfl_xor_sync(0xffffffffu, s, o);
    if ((t & 31) == 0) sh[t >> 5] = s;
    __syncthreads();
    if (t < 32) {
        float x = (t < 8) ? sh[t] : 0.f;
        #pragma unroll
        for (int o = 4; o > 0; o >>= 1) x += __shfl_xor_sync(0xffffffffu, x, o);
        if (t == 0) sh[0] = x;
    }
    __syncthreads();
    const float inv = 1.0f / sh[0];
    #pragma unroll
    for (int i = 0; i < 4; i++) {
        int idx = t + i * 256;
        if (idx < 960) p[idx] = v[i] * inv;
    }
}

static inline void launch_gemm(
    const float* A, int Am, int Ak, long sAz,
    const float* B, int Bn, int Bk, long sBz, int modB,
    float* C, int Cm, int Cn, long sCz,
    int M, int N, int K, int nbatch, float alpha)
{
    dim3 grid((N + BN - 1) / BN, (M + BM - 1) / BM, nbatch);
    gemm_tc<<<grid, 256>>>(A, Am, Ak, sAz, B, Bn, Bk, sBz, modB,
                           C, Cm, Cn, sCz, M, N, K, alpha);
}

extern "C" void kernel_launch(void* const* d_in, const int* in_sizes, int n_in,
                              void* d_out, int out_size)
{
    (void)in_sizes; (void)n_in; (void)out_size;

    const float* Q[4]  = {(const float*)d_in[0], (const float*)d_in[1],
                          (const float*)d_in[2], (const float*)d_in[3]};
    const float* KV    = (const float*)d_in[4];
    const float* Wk    = (const float*)d_in[5];
    const float* Wv    = (const float*)d_in[6];
    const float* Wq[4] = {(const float*)d_in[7], (const float*)d_in[8],
                          (const float*)d_in[9], (const float*)d_in[10]};
    const float* Wo[4] = {(const float*)d_in[11], (const float*)d_in[12],
                          (const float*)d_in[13], (const float*)d_in[14]};
    float* out = (float*)d_out;

    float *Kt, *KVt, *Qt, *attn, *ot, *part, *invstd;
    cudaGetSymbolAddress((void**)&Kt,     g_Kt);
    cudaGetSymbolAddress((void**)&KVt,    g_KVt);
    cudaGetSymbolAddress((void**)&Qt,     g_Qt);
    cudaGetSymbolAddress((void**)&attn,   g_attn);
    cudaGetSymbolAddress((void**)&ot,     g_outtmp);
    cudaGetSymbolAddress((void**)&part,   g_part);
    cudaGetSymbolAddress((void**)&invstd, g_invstd);

    const int S = 960, NSEQ = 128, BH = 64;
    const long sKV = (long)NSEQ * S;
    const float inv_scale = 1.0f / sqrtf(960.0f);

    // 1) Kt = KVh @ Wk^T   (per bh: 128x960, K=960; weight per h)
    launch_gemm(KV, S, 1, sKV,  Wk, S, 1, (long)S * S, 8,
                Kt, S, 1, sKV,  NSEQ, S, S, BH, 1.0f);
    // 2) KVt = Kt @ Wv^T
    launch_gemm(Kt, S, 1, sKV,  Wv, S, 1, (long)S * S, 8,
                KVt, S, 1, sKV, NSEQ, S, S, BH, 1.0f);

    const int  Cqs[4]    = {64, 128, 256, 512};
    const long outoff[4] = {0, 524288, 1572864, 3670016};

    for (int br = 0; br < 4; br++) {
        const int  Cq  = Cqs[br];
        const long sQ  = (long)NSEQ * Cq;
        const long sAt = (long)Cq * S;

        // 3) Qt = Qh @ Wq^T  (per bh: 128xCq, K=Cq)
        launch_gemm(Q[br], Cq, 1, sQ,  Wq[br], Cq, 1, (long)Cq * Cq, 8,
                    Qt, Cq, 1, sQ,  NSEQ, Cq, Cq, BH, 1.0f);

        // 4) attn = inv_scale * Qt^T @ KVt  (per bh: Cq x 960, K=128)
        launch_gemm(Qt, 1, Cq, sQ,  KVt, 1, S, sKV, BH,
                    attn, S, 1, sAt,  Cq, S, NSEQ, BH, inv_scale);

        // 5) per-slice inv_std, then row softmax of attn * inv_std
        {
            dim3 gp(16, BH);
            stats_partial<<<gp, 256>>>(attn, Cq * S, part);
            stats_final<<<1, 64>>>(part, invstd, 1.0f / (float)(Cq * S));
            dim3 gs(Cq, BH);
            softmax_kernel<<<gs, 256>>>(attn, invstd, Cq);
        }

        // 6) out = P @ KVt^T  (per bh: Cq x 128, K=960), stored transposed
        launch_gemm(attn, S, 1, sAt,  KVt, S, 1, sKV, BH,
                    ot, 1, Cq, (long)NSEQ * Cq,  Cq, NSEQ, S, BH, 1.0f);

        // 7) y = ot @ Wo^T  (per b: 1024 x Cq, K=Cq; shared weight)
        launch_gemm(ot, Cq, 1, (long)1024 * Cq,  Wo[br], Cq, 1, 0, 1,
                    out + outoff[br], Cq, 1, (long)1024 * Cq,
                    1024, Cq, Cq, 8, 1.0f);
    }
}

// round 6
// speedup vs baseline: 3.0073x; 1.3350x over previous
#include <cuda_runtime.h>
#include <cuda_bf16.h>
#include <math.h>
#include <stdint.h>

// ---------------------------------------------------------------------------
// MultiHeadCrossAttention — tf32 tensor-core GEMMs (mma.sync m16n8k8, fp32 acc)
// with fused InstanceNorm-stats (GEMM4 epilogue) and fused softmax (GEMM6).
//
// Shapes: B=8, N=1024, H=8, n=128, SCALE=960, Cq in {64,128,256,512}.
//
//   Kt   = KVh @ Wk^T                  (per b,h: 128x960, K=960)
//   KVt  = Kt  @ Wv^T                  (per b,h: 128x960, K=960)   (K == V)
//   per branch:
//     Qt   = Qh @ Wq^T                 (per b,h: 128xCq,  K=Cq)
//     attn = inv_scale * Qt^T @ KVt    (per b,h: Cq x 960, K=128)  [+ stats]
//     out  = softmax(attn*r - shift) @ KVt^T   (fused; per b,h: Cq x 128, K=960)
//     y    = out @ Wo^T                (per b: 1024 x Cq, K=Cq)
// ---------------------------------------------------------------------------

#define BM 128
#define BN 128
#define BK 16
#define SKS 20   // smem row stride in words: 80B = 5*16B (STS.128-aligned,
                 // (r*20+c) mod 32 distinct over frag lanes -> conflict-free)
#define LOG2E 1.44269504088896f

// Scratch (static device globals: allocation-free per harness rules)
__device__ float g_Kt    [8 * 1024 * 960];      // 31.5 MB
__device__ float g_KVt   [8 * 1024 * 960];      // 31.5 MB
__device__ float g_Qt    [8 * 1024 * 512];      // 16.8 MB
__device__ float g_attn  [64 * 512 * 960];      // 125.8 MB
__device__ float g_outtmp[8 * 1024 * 512];      // 16.8 MB
__device__ float g_part  [64 * 32 * 2];
__device__ float g_norm  [64 * 2];              // per slice: [invstd, mean*invstd]

__device__ __forceinline__ uint32_t f2tf(float x) {
    uint32_t r; asm("cvt.rna.tf32.f32 %0, %1;" : "=r"(r) : "f"(x)); return r;
}

__device__ __forceinline__ void mma8(float* c, const uint32_t* a, const uint32_t* b) {
    asm volatile("mma.sync.aligned.m16n8k8.row.col.f32.tf32.tf32.f32 "
        "{%0,%1,%2,%3}, {%4,%5,%6,%7}, {%8,%9}, {%0,%1,%2,%3};"
        : "+f"(c[0]), "+f"(c[1]), "+f"(c[2]), "+f"(c[3])
        : "r"(a[0]), "r"(a[1]), "r"(a[2]), "r"(a[3]), "r"(b[0]), "r"(b[1]));
}

// Load one 128x16 tile into registers (Xk==1: float4 along k; Xm==1: 4x LDG.32
// lane-coalesced along m). Rows clamped to [0, Mlim); clamped rows are never stored.
__device__ __forceinline__ void ldg_tile(
    const float* __restrict__ X, int Xm, int Xk,
    int m0, int k0, int Mlim, int tid, float* r)
{
    if (Xk == 1) {
        #pragma unroll
        for (int i = 0; i < 2; i++) {
            int q = tid + i * 256;
            int m = q >> 2, kq = q & 3;
            int mm = min(m0 + m, Mlim - 1);
            float4 v = *reinterpret_cast<const float4*>(X + (long)mm * Xm + k0 + kq * 4);
            r[i*4+0] = v.x; r[i*4+1] = v.y; r[i*4+2] = v.z; r[i*4+3] = v.w;
        }
    } else { // Xm == 1
        #pragma unroll
        for (int i = 0; i < 2; i++) {
            int q = tid + i * 256;
            int m = q & 127, kq = q >> 7;
            int mm = min(m0 + m, Mlim - 1);
            #pragma unroll
            for (int j = 0; j < 4; j++)
                r[i*4+j] = X[mm + (long)(k0 + kq * 4 + j) * Xk];
        }
    }
}

__device__ __forceinline__ void sts_tile(
    uint32_t (*S)[SKS], int Xk, int tid, const float* r)
{
    #pragma unroll
    for (int i = 0; i < 2; i++) {
        int q = tid + i * 256;
        int m, kq;
        if (Xk == 1) { m = q >> 2;  kq = q & 3; }
        else         { m = q & 127; kq = q >> 7; }
        uint4 v = make_uint4(f2tf(r[i*4+0]), f2tf(r[i*4+1]),
                             f2tf(r[i*4+2]), f2tf(r[i*4+3]));
        *reinterpret_cast<uint4*>(&S[m][kq * 4]) = v;
    }
}

// MODE 0: plain GEMM.
// MODE 1: + epilogue stats: per-CTA (sum, sumsq) of valid stored C -> part[].
// MODE 2: A-side fused softmax: a = exp(A*r - shift), per-row sums accumulated
//         deterministically; epilogue divides by row sum. (A path requires Ak==1.)
template <int MODE>
__global__ __launch_bounds__(256, 2) void gemm_tc(
    const float* __restrict__ A, int Am, int Ak, long sAz,
    const float* __restrict__ B, int Bn, int Bk, long sBz, int modB,
    float* __restrict__ C, int Cm, int Cn, long sCz,
    int M, int N, int K, float alpha,
    float* __restrict__ part, const float* __restrict__ norm)
{
    const int z = blockIdx.z;
    A += (long)z * sAz;
    B += (long)(z % modB) * sBz;
    C += (long)z * sCz;

    __shared__ uint32_t As[2][BM][SKS];
    __shared__ uint32_t Bs[2][BN][SKS];
    __shared__ float rsum[BM];

    const int tid  = threadIdx.x;
    const int lane = tid & 31;
    const int warp = tid >> 5;
    const int wm   = (warp & 1) * 64;
    const int wn   = (warp >> 1) * 32;
    const int m0   = blockIdx.y * BM;
    const int n0   = blockIdx.x * BN;

    const int gr = lane >> 2;
    const int gc = lane & 3;

    float nrm_r = 1.f, nrm_sh = 0.f;
    if (MODE == 2) { nrm_r = norm[z * 2]; nrm_sh = norm[z * 2 + 1]; }

    float acc[4][4][4];
    #pragma unroll
    for (int i = 0; i < 4; i++)
        #pragma unroll
        for (int j = 0; j < 4; j++)
            #pragma unroll
            for (int l = 0; l < 4; l++) acc[i][j][l] = 0.f;

    float rs0 = 0.f, rs1 = 0.f;   // MODE2 per-thread row partial sums
    float ra[8], rb[8];

    // A-side stage: convert (MODE<2) or exp-transform + rowsum (MODE2)
    auto stageA = [&](int p) {
        if (MODE == 2) {
            #pragma unroll
            for (int i = 0; i < 2; i++) {
                int q = tid + i * 256;
                int m = q >> 2, kq = q & 3;
                float e[4];
                #pragma unroll
                for (int j = 0; j < 4; j++)
                    e[j] = exp2f((ra[i*4+j] * nrm_r - nrm_sh) * LOG2E);
                float sloc = ((e[0] + e[1]) + (e[2] + e[3]));
                if (i == 0) rs0 += sloc; else rs1 += sloc;
                uint4 v = make_uint4(f2tf(e[0]), f2tf(e[1]), f2tf(e[2]), f2tf(e[3]));
                *reinterpret_cast<uint4*>(&As[p][m][kq * 4]) = v;
            }
        } else {
            sts_tile(As[p], Ak, tid, ra);
        }
    };

    // prologue: tile 0
    ldg_tile(A, Am, Ak, m0, 0, M, tid, ra);
    ldg_tile(B, Bn, Bk, n0, 0, N, tid, rb);
    stageA(0);
    sts_tile(Bs[0], Bk, tid, rb);
    __syncthreads();

    int p = 0;
    for (int k0 = BK; k0 <= K; k0 += BK) {
        const bool has_next = (k0 < K);
        if (has_next) {
            ldg_tile(A, Am, Ak, m0, k0, M, tid, ra);
            ldg_tile(B, Bn, Bk, n0, k0, N, tid, rb);
        }

        #pragma unroll
        for (int ks = 0; ks < 2; ks++) {
            const int kb = ks * 8;
            uint32_t af[4][4], bf[4][2];
            #pragma unroll
            for (int mt = 0; mt < 4; mt++) {
                const int r0 = wm + mt * 16 + gr;
                af[mt][0] = As[p][r0    ][kb + gc];
                af[mt][1] = As[p][r0 + 8][kb + gc];
                af[mt][2] = As[p][r0    ][kb + gc + 4];
                af[mt][3] = As[p][r0 + 8][kb + gc + 4];
            }
            #pragma unroll
            for (int nt = 0; nt < 4; nt++) {
                const int c0 = wn + nt * 8 + gr;
                bf[nt][0] = Bs[p][c0][kb + gc];
                bf[nt][1] = Bs[p][c0][kb + gc + 4];
            }
            #pragma unroll
            for (int mt = 0; mt < 4; mt++)
                #pragma unroll
                for (int nt = 0; nt < 4; nt++)
                    mma8(acc[mt][nt], af[mt], bf[nt]);
        }

        if (has_next) {
            stageA(p ^ 1);
            sts_tile(Bs[p ^ 1], Bk, tid, rb);
            __syncthreads();
            p ^= 1;
        }
    }

    if (MODE == 2) {
        // combine the 4 lanes sharing each A row (fixed butterfly order)
        #pragma unroll
        for (int o = 1; o <= 2; o <<= 1) {
            rs0 += __shfl_xor_sync(0xffffffffu, rs0, o);
            rs1 += __shfl_xor_sync(0xffffffffu, rs1, o);
        }
        __syncthreads();  // all frag reads of As/Bs done before rsum reuse
        if ((tid & 3) == 0) {
            rsum[tid >> 2]        = rs0;
            rsum[64 + (tid >> 2)] = rs1;
        }
        __syncthreads();
    }

    // epilogue (guarded)
    float psum = 0.f, psumsq = 0.f;
    #pragma unroll
    for (int mt = 0; mt < 4; mt++) {
        #pragma unroll
        for (int nt = 0; nt < 4; nt++) {
            const int rr = wm + mt * 16 + gr;
            const int cc = wn + nt * 8 + gc * 2;
            #pragma unroll
            for (int h = 0; h < 2; h++) {
                const int row = m0 + rr + h * 8;
                if (row < M) {
                    float scale = alpha;
                    if (MODE == 2) scale = 1.0f / rsum[rr + h * 8];
                    const int c1 = n0 + cc, c2 = n0 + cc + 1;
                    if (c1 < N) {
                        float v = scale * acc[mt][nt][h*2+0];
                        C[(long)row * Cm + (long)c1 * Cn] = v;
                        if (MODE == 1) { psum += v; psumsq += v * v; }
                    }
                    if (c2 < N) {
                        float v = scale * acc[mt][nt][h*2+1];
                        C[(long)row * Cm + (long)c2 * Cn] = v;
                        if (MODE == 1) { psum += v; psumsq += v * v; }
                    }
                }
            }
        }
    }

    if (MODE == 1) {
        // deterministic block reduction -> one partial per CTA
        __shared__ float shs[8], shss[8];
        #pragma unroll
        for (int o = 16; o > 0; o >>= 1) {
            psum   += __shfl_xor_sync(0xffffffffu, psum,   o);
            psumsq += __shfl_xor_sync(0xffffffffu, psumsq, o);
        }
        if (lane == 0) { shs[warp] = psum; shss[warp] = psumsq; }
        __syncthreads();
        if (tid == 0) {
            float S = 0.f, SS = 0.f;
            #pragma unroll
            for (int i = 0; i < 8; i++) { S += shs[i]; SS += shss[i]; }
            const int ctaPerZ = gridDim.x * gridDim.y;
            const long idx = (long)z * ctaPerZ + blockIdx.y * gridDim.x + blockIdx.x;
            part[idx * 2 + 0] = S;
            part[idx * 2 + 1] = SS;
        }
    }
}

// Fold per-CTA partials into invstd and shift = mean*invstd for each slice.
__global__ void stats_final(const float* __restrict__ part,
                            float* __restrict__ norm, int ctaPerZ, float inv_n)
{
    const int z = threadIdx.x;
    if (z < 64) {
        float s = 0.f, ss = 0.f;
        for (int i = 0; i < ctaPerZ; i++) {
            s  += part[((long)z * ctaPerZ + i) * 2 + 0];
            ss += part[((long)z * ctaPerZ + i) * 2 + 1];
        }
        const float m = s * inv_n;
        const float var = ss * inv_n - m * m;
        const float r = rsqrtf(var + 1e-5f);
        norm[z * 2 + 0] = r;
        norm[z * 2 + 1] = m * r;
    }
}

template <int MODE>
static inline void launch_gemm(
    const float* A, int Am, int Ak, long sAz,
    const float* B, int Bn, int Bk, long sBz, int modB,
    float* C, int Cm, int Cn, long sCz,
    int M, int N, int K, int nbatch, float alpha,
    float* part, const float* norm)
{
    dim3 grid((N + BN - 1) / BN, (M + BM - 1) / BM, nbatch);
    gemm_tc<MODE><<<grid, 256>>>(A, Am, Ak, sAz, B, Bn, Bk, sBz, modB,
                                 C, Cm, Cn, sCz, M, N, K, alpha, part, norm);
}

extern "C" void kernel_launch(void* const* d_in, const int* in_sizes, int n_in,
                              void* d_out, int out_size)
{
    (void)in_sizes; (void)n_in; (void)out_size;

    const float* Q[4]  = {(const float*)d_in[0], (const float*)d_in[1],
                          (const float*)d_in[2], (const float*)d_in[3]};
    const float* KV    = (const float*)d_in[4];
    const float* Wk    = (const float*)d_in[5];
    const float* Wv    = (const float*)d_in[6];
    const float* Wq[4] = {(const float*)d_in[7], (const float*)d_in[8],
                          (const float*)d_in[9], (const float*)d_in[10]};
    const float* Wo[4] = {(const float*)d_in[11], (const float*)d_in[12],
                          (const float*)d_in[13], (const float*)d_in[14]};
    float* out = (float*)d_out;

    float *Kt, *KVt, *Qt, *attn, *ot, *part, *norm;
    cudaGetSymbolAddress((void**)&Kt,   g_Kt);
    cudaGetSymbolAddress((void**)&KVt,  g_KVt);
    cudaGetSymbolAddress((void**)&Qt,   g_Qt);
    cudaGetSymbolAddress((void**)&attn, g_attn);
    cudaGetSymbolAddress((void**)&ot,   g_outtmp);
    cudaGetSymbolAddress((void**)&part, g_part);
    cudaGetSymbolAddress((void**)&norm, g_norm);

    const int S = 960, NSEQ = 128, BH = 64;
    const long sKV = (long)NSEQ * S;
    const float inv_scale = 1.0f / sqrtf(960.0f);

    // 1) Kt = KVh @ Wk^T   (per bh: 128x960, K=960; weight per h)
    launch_gemm<0>(KV, S, 1, sKV,  Wk, S, 1, (long)S * S, 8,
                   Kt, S, 1, sKV,  NSEQ, S, S, BH, 1.0f, nullptr, nullptr);
    // 2) KVt = Kt @ Wv^T
    launch_gemm<0>(Kt, S, 1, sKV,  Wv, S, 1, (long)S * S, 8,
                   KVt, S, 1, sKV, NSEQ, S, S, BH, 1.0f, nullptr, nullptr);

    const int  Cqs[4]    = {64, 128, 256, 512};
    const long outoff[4] = {0, 524288, 1572864, 3670016};

    for (int br = 0; br < 4; br++) {
        const int  Cq  = Cqs[br];
        const long sQ  = (long)NSEQ * Cq;
        const long sAt = (long)Cq * S;

        // 3) Qt = Qh @ Wq^T  (per bh: 128xCq, K=Cq)
        launch_gemm<0>(Q[br], Cq, 1, sQ,  Wq[br], Cq, 1, (long)Cq * Cq, 8,
                       Qt, Cq, 1, sQ,  NSEQ, Cq, Cq, BH, 1.0f, nullptr, nullptr);

        // 4) attn = inv_scale * Qt^T @ KVt  (per bh: Cq x 960, K=128)
        //    + fused per-CTA stats partials
        launch_gemm<1>(Qt, 1, Cq, sQ,  KVt, 1, S, sKV, BH,
                       attn, S, 1, sAt,  Cq, S, NSEQ, BH, inv_scale,
                       part, nullptr);

        // 5) fold partials -> invstd, shift
        {
            const int ctaPerZ = ((S + BN - 1) / BN) * ((Cq + BM - 1) / BM);
            stats_final<<<1, 64>>>(part, norm, ctaPerZ, 1.0f / (float)(Cq * S));
        }

        // 6) out = softmax(attn*r - shift) @ KVt^T  (fused; per bh: Cq x 128,
        //    K=960), stored transposed: ot[b, h*128+n, c]
        launch_gemm<2>(attn, S, 1, sAt,  KVt, S, 1, sKV, BH,
                       ot, 1, Cq, (long)NSEQ * Cq,  Cq, NSEQ, S, BH, 1.0f,
                       nullptr, norm);

        // 7) y = ot @ Wo^T  (per b: 1024 x Cq, K=Cq; shared weight)
        launch_gemm<0>(ot, Cq, 1, (long)1024 * Cq,  Wo[br], Cq, 1, 0, 1,
                       out + outoff[br], Cq, 1, (long)1024 * Cq,
                       1024, Cq, Cq, 8, 1.0f, nullptr, nullptr);
    }
}